// round 6
// baseline (speedup 1.0000x reference)
#include <cuda_runtime.h>
#include <cstddef>
#include <cstdint>

// Problem constants: B=2, S=512, H=256, A=128
#define BB 2
#define SS 512
#define HH 256
#define AA 128
#define HCH 8          // h-columns per scan block
#define XPAD 516       // smem row pitch for scan transpose

#define CH 16          // h per w-chunk in k_score
#define NCHUNK (HH / CH)   // 16 chunks

// Scratch (device globals; no allocs allowed)
__device__ float g_s[BB * SS];          // raw scores s[b,j]
__device__ float g_w[BB * SS];          // e_j * am_j
__device__ float g_scale[BB * SS];      // am_i / C_i

// ---------------------------------------------------------------------------
// Kernel 1: s[b,j] = sum_a query[a] * tanh( sum_h x[b,j,h] * w_a[h,a] )
// grid 128 (8 rows/block), block 512 (16 warps).
// w_a streamed via cp.async into a triple-buffered smem ring (reg-decoupled).
// warp = (g = h-quarter within chunk, q = col-quarter); lane owns ONE column;
// rows packed pairwise into f32x2 accumulators. No w-read redundancy.
// ---------------------------------------------------------------------------
__global__ __launch_bounds__(512) void k_score(
    const float* __restrict__ x, const float* __restrict__ w_a,
    const float* __restrict__ query)
{
    __shared__ float pool[8192];          // 32 KB: wbuf(3*2048) + xsT(2048); re-used as sred
    __shared__ float part[16][2];
    float* wbuf = pool;                   // 3 slots * CH*AA floats
    float* xsT  = pool + 3 * CH * AA;     // [h*8 + r]

    const int tid  = threadIdx.x;
    const int lane = tid & 31;
    const int wid  = tid >> 5;
    const int g    = wid >> 2;            // h-quarter of chunk (4 h each)
    const int q    = wid & 3;             // col-quarter (32 cols)
    const int r0   = blockIdx.x * 8;

    // stage 8 rows of x transposed: xsT[h*8 + r]
    {
        const int r  = tid & 7;
        const int h4 = tid >> 3;          // 0..63
        const float4 v =
            reinterpret_cast<const float4*>(x + (size_t)r0 * HH)[r * 64 + h4];
        xsT[(h4 * 4 + 0) * 8 + r] = v.x;
        xsT[(h4 * 4 + 1) * 8 + r] = v.y;
        xsT[(h4 * 4 + 2) * 8 + r] = v.z;
        xsT[(h4 * 4 + 3) * 8 + r] = v.w;
    }

    const uint32_t wdst_base =
        (uint32_t)__cvta_generic_to_shared(wbuf) + (uint32_t)tid * 16u;
    const float* wsrc_base = w_a + (size_t)tid * 4;

#define CP_ISSUE(c)                                                          \
    asm volatile(                                                            \
        "cp.async.cg.shared.global [%0], [%1], 16;\n\t"                      \
        "cp.async.commit_group;"                                             \
        :: "r"(wdst_base + (uint32_t)((c) % 3) * (CH * AA * 4u)),            \
           "l"(wsrc_base + (size_t)(c) * (CH * AA)) : "memory")

    CP_ISSUE(0);
    CP_ISSUE(1);

    // accumulators: 4 f32x2, packing row pairs (0,1)(2,3)(4,5)(6,7)
    unsigned long long acc0 = 0, acc1 = 0, acc2 = 0, acc3 = 0;

#pragma unroll
    for (int c = 0; c < NCHUNK; ++c) {
        if (c < NCHUNK - 1) asm volatile("cp.async.wait_group 1;" ::: "memory");
        else                asm volatile("cp.async.wait_group 0;" ::: "memory");
        __syncthreads();

        const float* wb = wbuf + (c % 3) * (CH * AA);
#pragma unroll
        for (int k = 0; k < 4; ++k) {
            const int hl = g * 4 + k;
            const int h  = c * CH + hl;
            const float wv = wb[hl * AA + q * 32 + lane];   // LDS.32, conflict-free
            unsigned long long wd;
            asm("mov.b64 %0, {%1, %1};" : "=l"(wd) : "f"(wv));
            const unsigned long long* xr =
                reinterpret_cast<const unsigned long long*>(xsT + h * 8);
            const unsigned long long x01 = xr[0];   // broadcast LDS.64
            const unsigned long long x23 = xr[1];
            const unsigned long long x45 = xr[2];
            const unsigned long long x67 = xr[3];
            asm("fma.rn.f32x2 %0, %1, %2, %0;" : "+l"(acc0) : "l"(x01), "l"(wd));
            asm("fma.rn.f32x2 %0, %1, %2, %0;" : "+l"(acc1) : "l"(x23), "l"(wd));
            asm("fma.rn.f32x2 %0, %1, %2, %0;" : "+l"(acc2) : "l"(x45), "l"(wd));
            asm("fma.rn.f32x2 %0, %1, %2, %0;" : "+l"(acc3) : "l"(x67), "l"(wd));
        }
        if (c + 2 < NCHUNK) CP_ISSUE(c + 2);
    }
#undef CP_ISSUE

    // re-use pool as sred[g][j][col] of float2 (rows 2j,2j+1): 4*4*128 float2
    __syncthreads();
    {
        float2* sred = reinterpret_cast<float2*>(pool);
        const int cbase = (g * 4) * AA + q * 32 + lane;
        unsigned long long av[4] = {acc0, acc1, acc2, acc3};
#pragma unroll
        for (int j = 0; j < 4; ++j) {
            float lo, hi;
            asm("mov.b64 {%0, %1}, %2;" : "=f"(lo), "=f"(hi) : "l"(av[j]));
            sred[cbase + j * AA] = make_float2(lo, hi);
        }
    }
    __syncthreads();

    // epilogue: thread = (row-pair j = tid>>7, col c = tid&127)
    {
        const float2* sred = reinterpret_cast<const float2*>(pool);
        const int j  = tid >> 7;
        const int cc = tid & 127;
        float v0 = 0.f, v1 = 0.f;
#pragma unroll
        for (int gg = 0; gg < 4; ++gg) {
            const float2 t = sred[(gg * 4 + j) * AA + cc];
            v0 += t.x; v1 += t.y;
        }
        const float qv = query[cc];
        float slo = qv * tanhf(v0);
        float shi = qv * tanhf(v1);
#pragma unroll
        for (int o = 16; o > 0; o >>= 1) {
            slo += __shfl_down_sync(0xffffffffu, slo, o);
            shi += __shfl_down_sync(0xffffffffu, shi, o);
        }
        if (lane == 0) { part[wid][0] = slo; part[wid][1] = shi; }
    }
    __syncthreads();
    if (tid < 8) {
        const int j = tid >> 1;       // row-pair
        const int w0 = j * 4;
        g_s[r0 + tid] = part[w0][tid & 1] + part[w0 + 1][tid & 1]
                      + part[w0 + 2][tid & 1] + part[w0 + 3][tid & 1];
    }
}

// ---------------------------------------------------------------------------
// Kernel 2: per-batch max + exp + inclusive prefix sum (shfl warp scans).
// ---------------------------------------------------------------------------
__global__ __launch_bounds__(512) void k_scan(const int* __restrict__ amask)
{
    const int b = blockIdx.x, tid = threadIdx.x;
    const int lane = tid & 31, wid = tid >> 5;   // 16 warps
    __shared__ float wmax[16], wsum[16];

    const float sv = g_s[b * SS + tid];

    float m = sv;
#pragma unroll
    for (int o = 16; o > 0; o >>= 1) m = fmaxf(m, __shfl_xor_sync(0xffffffffu, m, o));
    if (lane == 0) wmax[wid] = m;
    __syncthreads();
    float M = wmax[0];
#pragma unroll
    for (int k = 1; k < 16; ++k) M = fmaxf(M, wmax[k]);

    const float e = expf(sv - M);

    float sc = e;
#pragma unroll
    for (int o = 1; o < 32; o <<= 1) {
        const float t = __shfl_up_sync(0xffffffffu, sc, o);
        if (lane >= o) sc += t;
    }
    if (lane == 31) wsum[wid] = sc;
    __syncthreads();
    float off = 0.f;
#pragma unroll
    for (int k = 0; k < 16; ++k)
        if (k < wid) off += wsum[k];

    const float C  = sc + off;
    const int   am = amask[b * SS + tid];
    g_w[b * SS + tid]     = am ? e : 0.f;
    g_scale[b * SS + tid] = am ? (1.f / C) : 0.f;
}

// ---------------------------------------------------------------------------
// Kernel 3 (fused): grid (256 + 32, B), 512 threads.
//  bx < 256 : write 2 rows of d (float2 stores).
//  bx >= 256: column-scan block computing a[b, :, h0..h0+7] directly.
// ---------------------------------------------------------------------------
__global__ __launch_bounds__(512) void k_fused(
    const float* __restrict__ x, float* __restrict__ d_out,
    float* __restrict__ a_out)
{
    const int b = blockIdx.y, tid = threadIdx.x;

    if (blockIdx.x < 256) {
        const int rp = tid >> 8;             // 0/1
        const int sl = tid & 255;            // float2 slot
        const int i  = blockIdx.x * 2 + rp;
        const float sc = g_scale[b * SS + i];
        const float2 w2 = reinterpret_cast<const float2*>(g_w + b * SS)[sl];
        const int j0 = sl * 2;
        float2 o;
        o.x = (j0     <= i) ? w2.x * sc : 0.f;
        o.y = (j0 + 1 <= i) ? w2.y * sc : 0.f;
        reinterpret_cast<float2*>(d_out + (size_t)(b * SS + i) * SS)[sl] = o;
        return;
    }

    // ---- a-scan part ----
    __shared__ float xt[HCH][XPAD];
    __shared__ float ws[SS], scs[SS];
    __shared__ float htot[HCH];

    const int h0 = (blockIdx.x - 256) * HCH;

    ws[tid]  = g_w[b * SS + tid];
    scs[tid] = g_scale[b * SS + tid];

    const float* xb = x + (size_t)b * SS * HH + h0;
#pragma unroll
    for (int it = 0; it < HCH; ++it) {
        const int flat = it * 512 + tid;     // 0..4095
        const int j  = flat >> 3;
        const int hh = flat & 7;
        xt[hh][j] = xb[(size_t)j * HH + hh];
    }
    __syncthreads();

    const int lane = tid & 31, wid = tid >> 5;
    const int hh   = wid >> 1;               // h-column 0..7
    const int half = wid & 1;                // j-half 0/1
    const int jb   = half * 256;

    float carry = 0.f;
    float vals[8];
#pragma unroll
    for (int k = 0; k < 8; ++k) {
        const int j = jb + k * 32 + lane;
        float v = xt[hh][j] * ws[j];
#pragma unroll
        for (int o = 1; o < 32; o <<= 1) {
            const float t = __shfl_up_sync(0xffffffffu, v, o);
            if (lane >= o) v += t;
        }
        v += carry;
        carry = __shfl_sync(0xffffffffu, v, 31);
        vals[k] = v;
    }
    if (half == 0 && lane == 31) htot[hh] = carry;
    __syncthreads();

    const float base = half ? htot[hh] : 0.f;
#pragma unroll
    for (int k = 0; k < 8; ++k) {
        const int j = jb + k * 32 + lane;
        xt[hh][j] = (vals[k] + base) * scs[j];
    }
    __syncthreads();

    float* ab = a_out + (size_t)b * SS * HH + h0;
#pragma unroll
    for (int it = 0; it < HCH; ++it) {
        const int flat = it * 512 + tid;
        const int j  = flat >> 3;
        const int h2 = flat & 7;
        ab[(size_t)j * HH + h2] = xt[h2][j];
    }
}

// ---------------------------------------------------------------------------
extern "C" void kernel_launch(void* const* d_in, const int* in_sizes, int n_in,
                              void* d_out, int out_size)
{
    const float* x     = (const float*)d_in[0];   // (B,S,H)
    const int*   amask = (const int*)  d_in[1];   // (B,S)
    const float* w_a   = (const float*)d_in[2];   // (H,A)
    const float* query = (const float*)d_in[3];   // (A,)

    float* out   = (float*)d_out;
    float* a_out = out;                                // (B,S,H) first
    float* dd    = out + (size_t)BB * SS * HH;         // (B,S,S) second

    k_score<<<(BB * SS) / 8, 512>>>(x, w_a, query);
    k_scan<<<BB, SS>>>(amask);
    k_fused<<<dim3(256 + HH / HCH, BB), 512>>>(x, dd, a_out);
}

// round 8
// speedup vs baseline: 1.1210x; 1.1210x over previous
#include <cuda_runtime.h>
#include <cstddef>
#include <cstdint>

// Problem constants: B=2, S=512, H=256, A=128
#define BB 2
#define SS 512
#define HH 256
#define AA 128
#define HCH 8          // h-columns per scan block
#define XPAD 516       // smem row pitch for scan transpose

// Scratch (device globals; no allocs allowed)
__device__ float g_s[BB * SS];          // raw scores s[b,j]
__device__ float g_w[BB * SS];          // e_j * am_j
__device__ float g_scale[BB * SS];      // am_i / C_i

// ---------------------------------------------------------------------------
// Kernel 1: s[b,j] = sum_a query[a] * tanh( sum_h x[b,j,h] * w_a[h,a] )
// grid 128 (8 rows/block), block 512 (16 warps).
// Warp = (h-range hr = wid>>1: 32 h, col-half ch = wid&1: 64 cols).
// Per-warp cp.async DOUBLE buffer, prefetch distance 1 (slot-safe):
//   ISSUE(c+1); wait_group<=1; COMPUTE(c)
// wait_group + __syncwarp only -- no block barriers in the mainloop.
// ---------------------------------------------------------------------------
__global__ __launch_bounds__(512) void k_score(
    const float* __restrict__ x, const float* __restrict__ w_a,
    const float* __restrict__ query)
{
    __shared__ float pool[10240];        // 40KB: xsT(2048) + staging(8192)/sred
    __shared__ float part[16][2];
    float* xsT = pool;                                   // [h*8 + r]
    float* stg = pool + 2048;                            // wid*512 + slot*256
    unsigned long long* sredU =
        reinterpret_cast<unsigned long long*>(pool + 2048);  // [hg*4+rp][col]

    const int tid  = threadIdx.x;
    const int lane = tid & 31;
    const int wid  = tid >> 5;
    const int hr   = wid >> 1;            // h-range 0..7 (32 h each)
    const int ch   = wid & 1;             // col-half 0/1 (64 cols)
    const int h0   = hr * 32;
    const int r0   = blockIdx.x * 8;

    // per-lane cp.async source/dest (lane covers 32B of each 4hx64col subchunk)
    const float* wsrc = w_a + (size_t)(h0 + (lane >> 3)) * AA
                            + ch * 64 + (lane & 7) * 8;
    const uint32_t wdst =
        (uint32_t)__cvta_generic_to_shared(stg + wid * 512 + lane * 8);

#define ISSUE(c)                                                             \
    asm volatile(                                                            \
        "cp.async.cg.shared.global [%0], [%1], 16;\n\t"                      \
        "cp.async.cg.shared.global [%2], [%3], 16;\n\t"                      \
        "cp.async.commit_group;"                                             \
        :: "r"(wdst + (uint32_t)(((c) & 1) * 1024)),                         \
           "l"(wsrc + (size_t)(c) * 4 * AA),                                 \
           "r"(wdst + (uint32_t)(((c) & 1) * 1024 + 16)),                    \
           "l"(wsrc + (size_t)(c) * 4 * AA + 4) : "memory")

    ISSUE(0);

    // stage 8 rows of x transposed: xsT[h*8 + r]
    {
        const int r  = tid & 7;
        const int h4 = tid >> 3;           // 0..63
        const float4 v =
            reinterpret_cast<const float4*>(x + (size_t)r0 * HH)[r * 64 + h4];
        xsT[(h4 * 4 + 0) * 8 + r] = v.x;
        xsT[(h4 * 4 + 1) * 8 + r] = v.y;
        xsT[(h4 * 4 + 2) * 8 + r] = v.z;
        xsT[(h4 * 4 + 3) * 8 + r] = v.w;
    }
    __syncthreads();                       // xsT ready (barrier #1)

    // acc[col-of-pair][row-pair] as packed f32x2
    unsigned long long acc00=0,acc01=0,acc02=0,acc03=0;
    unsigned long long acc10=0,acc11=0,acc12=0,acc13=0;

#define COMPUTE(c)                                                           \
    do {                                                                     \
        const float* wb = stg + wid * 512 + ((c) & 1) * 256;                 \
        _Pragma("unroll")                                                    \
        for (int hl = 0; hl < 4; ++hl) {                                     \
            const float2 w2 =                                                \
                *reinterpret_cast<const float2*>(wb + hl * 64 + lane * 2);   \
            unsigned long long wd0, wd1;                                     \
            asm("mov.b64 %0, {%1, %1};" : "=l"(wd0) : "f"(w2.x));            \
            asm("mov.b64 %0, {%1, %1};" : "=l"(wd1) : "f"(w2.y));            \
            const unsigned long long* xr =                                   \
                reinterpret_cast<const unsigned long long*>(                 \
                    xsT + (h0 + (c) * 4 + hl) * 8);                          \
            const unsigned long long x01 = xr[0];                            \
            const unsigned long long x23 = xr[1];                            \
            const unsigned long long x45 = xr[2];                            \
            const unsigned long long x67 = xr[3];                            \
            asm("fma.rn.f32x2 %0, %1, %2, %0;" : "+l"(acc00) : "l"(x01), "l"(wd0)); \
            asm("fma.rn.f32x2 %0, %1, %2, %0;" : "+l"(acc01) : "l"(x23), "l"(wd0)); \
            asm("fma.rn.f32x2 %0, %1, %2, %0;" : "+l"(acc02) : "l"(x45), "l"(wd0)); \
            asm("fma.rn.f32x2 %0, %1, %2, %0;" : "+l"(acc03) : "l"(x67), "l"(wd0)); \
            asm("fma.rn.f32x2 %0, %1, %2, %0;" : "+l"(acc10) : "l"(x01), "l"(wd1)); \
            asm("fma.rn.f32x2 %0, %1, %2, %0;" : "+l"(acc11) : "l"(x23), "l"(wd1)); \
            asm("fma.rn.f32x2 %0, %1, %2, %0;" : "+l"(acc12) : "l"(x45), "l"(wd1)); \
            asm("fma.rn.f32x2 %0, %1, %2, %0;" : "+l"(acc13) : "l"(x67), "l"(wd1)); \
        }                                                                    \
    } while (0)

#define WAITW(n) asm volatile("cp.async.wait_group " #n ";" ::: "memory"); __syncwarp()

    // prefetch distance 1: ISSUE(c+1) targets the OTHER slot; COMPUTE(c)
    // has already read slot c&1 before ISSUE(c+2) can touch it.
    ISSUE(1); WAITW(1); COMPUTE(0);
    ISSUE(2); WAITW(1); COMPUTE(1);
    ISSUE(3); WAITW(1); COMPUTE(2);
    ISSUE(4); WAITW(1); COMPUTE(3);
    ISSUE(5); WAITW(1); COMPUTE(4);
    ISSUE(6); WAITW(1); COMPUTE(5);
    ISSUE(7); WAITW(1); COMPUTE(6);
              WAITW(0); COMPUTE(7);
#undef ISSUE
#undef COMPUTE
#undef WAITW

    __syncthreads();                       // staging region free (barrier #2)

    // store partials: sredU[(hr*4+rp)*128 + col]
    {
        const int c0 = ch * 64 + lane * 2;
        unsigned long long a0[4] = {acc00, acc01, acc02, acc03};
        unsigned long long a1[4] = {acc10, acc11, acc12, acc13};
#pragma unroll
        for (int rp = 0; rp < 4; ++rp) {
            sredU[(hr * 4 + rp) * 128 + c0]     = a0[rp];
            sredU[(hr * 4 + rp) * 128 + c0 + 1] = a1[rp];
        }
    }
    __syncthreads();                       // sred ready (barrier #3)

    // epilogue: thread = (row-pair rp = tid>>7, col = tid&127)
    {
        const int rp  = tid >> 7;
        const int col = tid & 127;
        float v0 = 0.f, v1 = 0.f;
#pragma unroll
        for (int hg = 0; hg < 8; ++hg) {
            float lo, hi;
            asm("mov.b64 {%0, %1}, %2;" : "=f"(lo), "=f"(hi)
                : "l"(sredU[(hg * 4 + rp) * 128 + col]));
            v0 += lo; v1 += hi;
        }
        const float qv = query[col];
        float slo = qv * tanhf(v0);        // row 2*rp
        float shi = qv * tanhf(v1);        // row 2*rp+1
#pragma unroll
        for (int o = 16; o > 0; o >>= 1) {
            slo += __shfl_down_sync(0xffffffffu, slo, o);
            shi += __shfl_down_sync(0xffffffffu, shi, o);
        }
        if (lane == 0) { part[wid][0] = slo; part[wid][1] = shi; }
    }
    __syncthreads();
    if (tid < 8) {
        const int w0  = (tid >> 1) * 4;
        const int sel = tid & 1;
        g_s[r0 + tid] = part[w0][sel] + part[w0 + 1][sel]
                      + part[w0 + 2][sel] + part[w0 + 3][sel];
    }
}

// ---------------------------------------------------------------------------
// Kernel 2: per-batch max + exp + inclusive prefix sum (shfl warp scans).
// ---------------------------------------------------------------------------
__global__ __launch_bounds__(512) void k_scan(const int* __restrict__ amask)
{
    const int b = blockIdx.x, tid = threadIdx.x;
    const int lane = tid & 31, wid = tid >> 5;   // 16 warps
    __shared__ float wmax[16], wsum[16];

    const float sv = g_s[b * SS + tid];

    float m = sv;
#pragma unroll
    for (int o = 16; o > 0; o >>= 1) m = fmaxf(m, __shfl_xor_sync(0xffffffffu, m, o));
    if (lane == 0) wmax[wid] = m;
    __syncthreads();
    float M = wmax[0];
#pragma unroll
    for (int k = 1; k < 16; ++k) M = fmaxf(M, wmax[k]);

    const float e = expf(sv - M);

    float sc = e;
#pragma unroll
    for (int o = 1; o < 32; o <<= 1) {
        const float t = __shfl_up_sync(0xffffffffu, sc, o);
        if (lane >= o) sc += t;
    }
    if (lane == 31) wsum[wid] = sc;
    __syncthreads();
    float off = 0.f;
#pragma unroll
    for (int k = 0; k < 16; ++k)
        if (k < wid) off += wsum[k];

    const float C  = sc + off;
    const int   am = amask[b * SS + tid];
    g_w[b * SS + tid]     = am ? e : 0.f;
    g_scale[b * SS + tid] = am ? (1.f / C) : 0.f;
}

// ---------------------------------------------------------------------------
// Kernel 3 (fused): grid (256 + 32, B), 512 threads.
//  bx < 256 : write 2 rows of d (float2 stores).
//  bx >= 256: column-scan block computing a[b, :, h0..h0+7] directly.
// ---------------------------------------------------------------------------
__global__ __launch_bounds__(512) void k_fused(
    const float* __restrict__ x, float* __restrict__ d_out,
    float* __restrict__ a_out)
{
    const int b = blockIdx.y, tid = threadIdx.x;

    if (blockIdx.x < 256) {
        const int rp = tid >> 8;             // 0/1
        const int sl = tid & 255;            // float2 slot
        const int i  = blockIdx.x * 2 + rp;
        const float sc = g_scale[b * SS + i];
        const float2 w2 = reinterpret_cast<const float2*>(g_w + b * SS)[sl];
        const int j0 = sl * 2;
        float2 o;
        o.x = (j0     <= i) ? w2.x * sc : 0.f;
        o.y = (j0 + 1 <= i) ? w2.y * sc : 0.f;
        reinterpret_cast<float2*>(d_out + (size_t)(b * SS + i) * SS)[sl] = o;
        return;
    }

    // ---- a-scan part ----
    __shared__ float xt[HCH][XPAD];
    __shared__ float ws[SS], scs[SS];
    __shared__ float htot[HCH];

    const int h0 = (blockIdx.x - 256) * HCH;

    ws[tid]  = g_w[b * SS + tid];
    scs[tid] = g_scale[b * SS + tid];

    const float* xb = x + (size_t)b * SS * HH + h0;
#pragma unroll
    for (int it = 0; it < HCH; ++it) {
        const int flat = it * 512 + tid;     // 0..4095
        const int j  = flat >> 3;
        const int hh = flat & 7;
        xt[hh][j] = xb[(size_t)j * HH + hh];
    }
    __syncthreads();

    const int lane = tid & 31, wid = tid >> 5;
    const int hh   = wid >> 1;               // h-column 0..7
    const int half = wid & 1;                // j-half 0/1
    const int jb   = half * 256;

    float carry = 0.f;
    float vals[8];
#pragma unroll
    for (int k = 0; k < 8; ++k) {
        const int j = jb + k * 32 + lane;
        float v = xt[hh][j] * ws[j];
#pragma unroll
        for (int o = 1; o < 32; o <<= 1) {
            const float t = __shfl_up_sync(0xffffffffu, v, o);
            if (lane >= o) v += t;
        }
        v += carry;
        carry = __shfl_sync(0xffffffffu, v, 31);
        vals[k] = v;
    }
    if (half == 0 && lane == 31) htot[hh] = carry;
    __syncthreads();

    const float base = half ? htot[hh] : 0.f;
#pragma unroll
    for (int k = 0; k < 8; ++k) {
        const int j = jb + k * 32 + lane;
        xt[hh][j] = (vals[k] + base) * scs[j];
    }
    __syncthreads();

    float* ab = a_out + (size_t)b * SS * HH + h0;
#pragma unroll
    for (int it = 0; it < HCH; ++it) {
        const int flat = it * 512 + tid;
        const int j  = flat >> 3;
        const int h2 = flat & 7;
        ab[(size_t)j * HH + h2] = xt[h2][j];
    }
}

// ---------------------------------------------------------------------------
extern "C" void kernel_launch(void* const* d_in, const int* in_sizes, int n_in,
                              void* d_out, int out_size)
{
    const float* x     = (const float*)d_in[0];   // (B,S,H)
    const int*   amask = (const int*)  d_in[1];   // (B,S)
    const float* w_a   = (const float*)d_in[2];   // (H,A)
    const float* query = (const float*)d_in[3];   // (A,)

    float* out   = (float*)d_out;
    float* a_out = out;                                // (B,S,H) first
    float* dd    = out + (size_t)BB * SS * HH;         // (B,S,S) second

    k_score<<<(BB * SS) / 8, 512>>>(x, w_a, query);
    k_scan<<<BB, SS>>>(amask);
    k_fused<<<dim3(256 + HH / HCH, BB), 512>>>(x, dd, a_out);
}

// round 9
// speedup vs baseline: 1.1379x; 1.0151x over previous
#include <cuda_runtime.h>
#include <cstddef>
#include <cstdint>

// Problem constants: B=2, S=512, H=256, A=128
#define BB 2
#define SS 512
#define HH 256
#define AA 128
#define HCH 8          // h-columns per scan block
#define XPAD 516       // smem row pitch for scan transpose

// k_score dynamic smem: xsT (2048 floats) + staging (16 warps * 1024 floats)
#define KS_SMEM_FLOATS (2048 + 16 * 1024)
#define KS_SMEM_BYTES  (KS_SMEM_FLOATS * 4)

// Scratch (device globals; no allocs allowed)
__device__ float g_s[BB * SS];          // raw scores s[b,j]
__device__ float g_w[BB * SS];          // e_j * am_j
__device__ float g_scale[BB * SS];      // am_i / C_i

// ---------------------------------------------------------------------------
// Kernel 1: s[b,j] = sum_a query[a] * tanh( sum_h x[b,j,h] * w_a[h,a] )
// grid 128 (8 rows/block), block 512 (16 warps).
// Warp = (h-range hr = wid>>1: 32 h, col-half ch = wid&1: 64 cols).
// Per-warp cp.async 4-slot ring, prefetch distance 3 (wait_group 3):
// covered latency ~3 chunks of compute > L2 latency -> ~zero steady stall.
// ---------------------------------------------------------------------------
__global__ __launch_bounds__(512) void k_score(
    const float* __restrict__ x, const float* __restrict__ w_a,
    const float* __restrict__ query)
{
    extern __shared__ float pool[];      // 72KB: xsT(2048) + staging(16*1024)
    __shared__ float part[16][2];
    float* xsT = pool;                                   // [h*8 + r]
    float* stg = pool + 2048;                            // wid*1024 + slot*256
    unsigned long long* sredU =
        reinterpret_cast<unsigned long long*>(pool + 2048);  // reuse as [hg*4+rp][col]

    const int tid  = threadIdx.x;
    const int lane = tid & 31;
    const int wid  = tid >> 5;
    const int hr   = wid >> 1;            // h-range 0..7 (32 h each)
    const int ch   = wid & 1;             // col-half 0/1 (64 cols)
    const int h0   = hr * 32;
    const int r0   = blockIdx.x * 8;

    // per-lane cp.async source/dest: chunk = 4h x 64col = 1KB; lane owns 32B
    const float* wsrc = w_a + (size_t)(h0 + (lane >> 3)) * AA
                            + ch * 64 + (lane & 7) * 8;
    const uint32_t wdst =
        (uint32_t)__cvta_generic_to_shared(stg + wid * 1024 + lane * 8);

#define ISSUE(c)                                                             \
    asm volatile(                                                            \
        "cp.async.cg.shared.global [%0], [%1], 16;\n\t"                      \
        "cp.async.cg.shared.global [%2], [%3], 16;\n\t"                      \
        "cp.async.commit_group;"                                             \
        :: "r"(wdst + (uint32_t)(((c) & 3) * 1024)),                         \
           "l"(wsrc + (size_t)(c) * 4 * AA),                                 \
           "r"(wdst + (uint32_t)(((c) & 3) * 1024 + 16)),                    \
           "l"(wsrc + (size_t)(c) * 4 * AA + 4) : "memory")

    ISSUE(0); ISSUE(1); ISSUE(2); ISSUE(3);

    // stage 8 rows of x transposed: xsT[h*8 + r] (overlaps with prefetches)
    {
        const int r  = tid & 7;
        const int h4 = tid >> 3;           // 0..63
        const float4 v =
            reinterpret_cast<const float4*>(x + (size_t)r0 * HH)[r * 64 + h4];
        xsT[(h4 * 4 + 0) * 8 + r] = v.x;
        xsT[(h4 * 4 + 1) * 8 + r] = v.y;
        xsT[(h4 * 4 + 2) * 8 + r] = v.z;
        xsT[(h4 * 4 + 3) * 8 + r] = v.w;
    }
    __syncthreads();                       // xsT ready (barrier #1)

    // acc[col-of-pair][row-pair] as packed f32x2
    unsigned long long acc00=0,acc01=0,acc02=0,acc03=0;
    unsigned long long acc10=0,acc11=0,acc12=0,acc13=0;

#define COMPUTE(c)                                                           \
    do {                                                                     \
        const float* wb = stg + wid * 1024 + ((c) & 3) * 256;                \
        _Pragma("unroll")                                                    \
        for (int hl = 0; hl < 4; ++hl) {                                     \
            const float2 w2 =                                                \
                *reinterpret_cast<const float2*>(wb + hl * 64 + lane * 2);   \
            unsigned long long wd0, wd1;                                     \
            asm("mov.b64 %0, {%1, %1};" : "=l"(wd0) : "f"(w2.x));            \
            asm("mov.b64 %0, {%1, %1};" : "=l"(wd1) : "f"(w2.y));            \
            const unsigned long long* xr =                                   \
                reinterpret_cast<const unsigned long long*>(                 \
                    xsT + (h0 + (c) * 4 + hl) * 8);                          \
            const unsigned long long x01 = xr[0];                            \
            const unsigned long long x23 = xr[1];                            \
            const unsigned long long x45 = xr[2];                            \
            const unsigned long long x67 = xr[3];                            \
            asm("fma.rn.f32x2 %0, %1, %2, %0;" : "+l"(acc00) : "l"(x01), "l"(wd0)); \
            asm("fma.rn.f32x2 %0, %1, %2, %0;" : "+l"(acc01) : "l"(x23), "l"(wd0)); \
            asm("fma.rn.f32x2 %0, %1, %2, %0;" : "+l"(acc02) : "l"(x45), "l"(wd0)); \
            asm("fma.rn.f32x2 %0, %1, %2, %0;" : "+l"(acc03) : "l"(x67), "l"(wd0)); \
            asm("fma.rn.f32x2 %0, %1, %2, %0;" : "+l"(acc10) : "l"(x01), "l"(wd1)); \
            asm("fma.rn.f32x2 %0, %1, %2, %0;" : "+l"(acc11) : "l"(x23), "l"(wd1)); \
            asm("fma.rn.f32x2 %0, %1, %2, %0;" : "+l"(acc12) : "l"(x45), "l"(wd1)); \
            asm("fma.rn.f32x2 %0, %1, %2, %0;" : "+l"(acc13) : "l"(x67), "l"(wd1)); \
        }                                                                    \
    } while (0)

#define WAITW(n) asm volatile("cp.async.wait_group " #n ";" ::: "memory"); __syncwarp()

    // ring depth 4, distance 3. ISSUE(c+4) hits slot c&3 AFTER COMPUTE(c).
    WAITW(3); COMPUTE(0); ISSUE(4);
    WAITW(3); COMPUTE(1); ISSUE(5);
    WAITW(3); COMPUTE(2); ISSUE(6);
    WAITW(3); COMPUTE(3); ISSUE(7);
    WAITW(3); COMPUTE(4);
    WAITW(2); COMPUTE(5);
    WAITW(1); COMPUTE(6);
    WAITW(0); COMPUTE(7);
#undef ISSUE
#undef COMPUTE
#undef WAITW

    __syncthreads();                       // staging region free (barrier #2)

    // store partials: sredU[(hr*4+rp)*128 + col]
    {
        const int c0 = ch * 64 + lane * 2;
        unsigned long long a0[4] = {acc00, acc01, acc02, acc03};
        unsigned long long a1[4] = {acc10, acc11, acc12, acc13};
#pragma unroll
        for (int rp = 0; rp < 4; ++rp) {
            sredU[(hr * 4 + rp) * 128 + c0]     = a0[rp];
            sredU[(hr * 4 + rp) * 128 + c0 + 1] = a1[rp];
        }
    }
    __syncthreads();                       // sred ready (barrier #3)

    // epilogue: thread = (row-pair rp = tid>>7, col = tid&127)
    {
        const int rp  = tid >> 7;
        const int col = tid & 127;
        float v0 = 0.f, v1 = 0.f;
#pragma unroll
        for (int hg = 0; hg < 8; ++hg) {
            float lo, hi;
            asm("mov.b64 {%0, %1}, %2;" : "=f"(lo), "=f"(hi)
                : "l"(sredU[(hg * 4 + rp) * 128 + col]));
            v0 += lo; v1 += hi;
        }
        const float qv = query[col];
        float slo = qv * tanhf(v0);        // row 2*rp
        float shi = qv * tanhf(v1);        // row 2*rp+1
#pragma unroll
        for (int o = 16; o > 0; o >>= 1) {
            slo += __shfl_down_sync(0xffffffffu, slo, o);
            shi += __shfl_down_sync(0xffffffffu, shi, o);
        }
        if (lane == 0) { part[wid][0] = slo; part[wid][1] = shi; }
    }
    __syncthreads();
    if (tid < 8) {
        const int w0  = (tid >> 1) * 4;
        const int sel = tid & 1;
        g_s[r0 + tid] = part[w0][sel] + part[w0 + 1][sel]
                      + part[w0 + 2][sel] + part[w0 + 3][sel];
    }
}

// ---------------------------------------------------------------------------
// Kernel 2: per-batch max + exp + inclusive prefix sum (shfl warp scans).
// ---------------------------------------------------------------------------
__global__ __launch_bounds__(512) void k_scan(const int* __restrict__ amask)
{
    const int b = blockIdx.x, tid = threadIdx.x;
    const int lane = tid & 31, wid = tid >> 5;   // 16 warps
    __shared__ float wmax[16], wsum[16];

    const float sv = g_s[b * SS + tid];

    float m = sv;
#pragma unroll
    for (int o = 16; o > 0; o >>= 1) m = fmaxf(m, __shfl_xor_sync(0xffffffffu, m, o));
    if (lane == 0) wmax[wid] = m;
    __syncthreads();
    float M = wmax[0];
#pragma unroll
    for (int k = 1; k < 16; ++k) M = fmaxf(M, wmax[k]);

    const float e = expf(sv - M);

    float sc = e;
#pragma unroll
    for (int o = 1; o < 32; o <<= 1) {
        const float t = __shfl_up_sync(0xffffffffu, sc, o);
        if (lane >= o) sc += t;
    }
    if (lane == 31) wsum[wid] = sc;
    __syncthreads();
    float off = 0.f;
#pragma unroll
    for (int k = 0; k < 16; ++k)
        if (k < wid) off += wsum[k];

    const float C  = sc + off;
    const int   am = amask[b * SS + tid];
    g_w[b * SS + tid]     = am ? e : 0.f;
    g_scale[b * SS + tid] = am ? (1.f / C) : 0.f;
}

// ---------------------------------------------------------------------------
// Kernel 3 (fused): grid (256 + 32, B), 512 threads.
//  bx < 256 : write 2 rows of d (float2 stores).
//  bx >= 256: column-scan block computing a[b, :, h0..h0+7] directly.
// ---------------------------------------------------------------------------
__global__ __launch_bounds__(512) void k_fused(
    const float* __restrict__ x, float* __restrict__ d_out,
    float* __restrict__ a_out)
{
    const int b = blockIdx.y, tid = threadIdx.x;

    if (blockIdx.x < 256) {
        const int rp = tid >> 8;             // 0/1
        const int sl = tid & 255;            // float2 slot
        const int i  = blockIdx.x * 2 + rp;
        const float sc = g_scale[b * SS + i];
        const float2 w2 = reinterpret_cast<const float2*>(g_w + b * SS)[sl];
        const int j0 = sl * 2;
        float2 o;
        o.x = (j0     <= i) ? w2.x * sc : 0.f;
        o.y = (j0 + 1 <= i) ? w2.y * sc : 0.f;
        reinterpret_cast<float2*>(d_out + (size_t)(b * SS + i) * SS)[sl] = o;
        return;
    }

    // ---- a-scan part ----
    __shared__ float xt[HCH][XPAD];
    __shared__ float ws[SS], scs[SS];
    __shared__ float htot[HCH];

    const int h0 = (blockIdx.x - 256) * HCH;

    ws[tid]  = g_w[b * SS + tid];
    scs[tid] = g_scale[b * SS + tid];

    const float* xb = x + (size_t)b * SS * HH + h0;
#pragma unroll
    for (int it = 0; it < HCH; ++it) {
        const int flat = it * 512 + tid;     // 0..4095
        const int j  = flat >> 3;
        const int hh = flat & 7;
        xt[hh][j] = xb[(size_t)j * HH + hh];
    }
    __syncthreads();

    const int lane = tid & 31, wid = tid >> 5;
    const int hh   = wid >> 1;               // h-column 0..7
    const int half = wid & 1;                // j-half 0/1
    const int jb   = half * 256;

    float carry = 0.f;
    float vals[8];
#pragma unroll
    for (int k = 0; k < 8; ++k) {
        const int j = jb + k * 32 + lane;
        float v = xt[hh][j] * ws[j];
#pragma unroll
        for (int o = 1; o < 32; o <<= 1) {
            const float t = __shfl_up_sync(0xffffffffu, v, o);
            if (lane >= o) v += t;
        }
        v += carry;
        carry = __shfl_sync(0xffffffffu, v, 31);
        vals[k] = v;
    }
    if (half == 0 && lane == 31) htot[hh] = carry;
    __syncthreads();

    const float base = half ? htot[hh] : 0.f;
#pragma unroll
    for (int k = 0; k < 8; ++k) {
        const int j = jb + k * 32 + lane;
        xt[hh][j] = (vals[k] + base) * scs[j];
    }
    __syncthreads();

    float* ab = a_out + (size_t)b * SS * HH + h0;
#pragma unroll
    for (int it = 0; it < HCH; ++it) {
        const int flat = it * 512 + tid;
        const int j  = flat >> 3;
        const int h2 = flat & 7;
        ab[(size_t)j * HH + h2] = xt[h2][j];
    }
}

// ---------------------------------------------------------------------------
extern "C" void kernel_launch(void* const* d_in, const int* in_sizes, int n_in,
                              void* d_out, int out_size)
{
    const float* x     = (const float*)d_in[0];   // (B,S,H)
    const int*   amask = (const int*)  d_in[1];   // (B,S)
    const float* w_a   = (const float*)d_in[2];   // (H,A)
    const float* query = (const float*)d_in[3];   // (A,)

    float* out   = (float*)d_out;
    float* a_out = out;                                // (B,S,H) first
    float* dd    = out + (size_t)BB * SS * HH;         // (B,S,S) second

    // allow 72KB dynamic smem for k_score (host-side attr, capture-safe)
    cudaFuncSetAttribute(k_score, cudaFuncAttributeMaxDynamicSharedMemorySize,
                         KS_SMEM_BYTES);

    k_score<<<(BB * SS) / 8, 512, KS_SMEM_BYTES>>>(x, w_a, query);
    k_scan<<<BB, SS>>>(amask);
    k_fused<<<dim3(256 + HH / HCH, BB), 512>>>(x, dd, a_out);
}